// round 5
// baseline (speedup 1.0000x reference)
#include <cuda_runtime.h>
#include <cstdint>

#define T_TOKENS 16384
#define DIMX     2048
#define NE       8
#define KSEL     2048

// libdevice exp — exact bits, immune to fast-math flags.
extern "C" __device__ float __nv_expf(float);

// Scratch: per-expert sort keys, key = ~bits(sigmoid(logit)). [e][t]
__device__ unsigned int g_keys[NE * T_TOKENS];

// ---------------------------------------------------------------------------
// Kernel 1: logits + keys. 8 threads per token; thread (t,e) runs the full
// 2048-dim in-order scalar fma.rn chain (bitwise identical to R4).
// chunk=128 dims (4 float4 prefetch/thread, 16 chunks, 32 barriers) and
// __launch_bounds__(512,2) to guarantee 2 blocks/SM (8 warps/SMSP).
// ---------------------------------------------------------------------------
#define TILE_T     64
#define K1_THREADS 512
#define CHUNK      128
#define XPITCH     132   // 128 + 4 pad: conflict-free broadcast LDS.128
#define WP         2052  // per-expert row pitch (bank skew 4e)

__global__ void __launch_bounds__(K1_THREADS, 2) k1_gemv(const float* __restrict__ x,
                                                         const float* __restrict__ W)
{
    extern __shared__ float sm1[];
    float* sw = sm1;                 // [NE][WP]          ~65.7 KB
    float* sx = sm1 + NE * WP;       // [TILE_T][XPITCH]  ~33.8 KB

    const int tid = threadIdx.x;

    // Load W rows (coalesced LDG, coalesced STS).
    for (int i = tid; i < NE * DIMX; i += K1_THREADS) {
        int e = i >> 11;
        int d = i & 2047;
        sw[e * WP + d] = W[i];
    }

    const int tloc = tid >> 3;       // token within tile (0..63)
    const int e    = tid & 7;        // expert
    const size_t rowBase = (size_t)blockIdx.x * TILE_T;
    const float* wrow = sw + e * WP;

    // Staging: 64 rows x 32 float4 per chunk = 2048 float4; 4 per thread.
    int rr[4], cc[4];
#pragma unroll
    for (int k = 0; k < 4; ++k) {
        int idx = tid + k * K1_THREADS;
        rr[k] = idx >> 5;
        cc[k] = idx & 31;
    }

    float4 p[4];
    {
        const float* base = x + rowBase * DIMX;
#pragma unroll
        for (int k = 0; k < 4; ++k)
            p[k] = *reinterpret_cast<const float4*>(base + (size_t)rr[k] * DIMX + cc[k] * 4);
    }

    float acc = 0.0f;

    for (int ch = 0; ch < DIMX / CHUNK; ++ch) {
        __syncthreads();   // prev compute done (and sw ready on ch==0)
#pragma unroll
        for (int k = 0; k < 4; ++k)
            *reinterpret_cast<float4*>(&sx[rr[k] * XPITCH + cc[k] * 4]) = p[k];
        __syncthreads();   // sx visible

        if (ch + 1 < DIMX / CHUNK) {   // prefetch next chunk; lands during compute
            const float* base = x + rowBase * DIMX + (ch + 1) * CHUNK;
#pragma unroll
            for (int k = 0; k < 4; ++k)
                p[k] = *reinterpret_cast<const float4*>(base + (size_t)rr[k] * DIMX + cc[k] * 4);
        }

        const float* xd = sx + tloc * XPITCH;
        const float* wd = wrow + ch * CHUNK;
#pragma unroll
        for (int c4 = 0; c4 < CHUNK / 4; ++c4) {
            float4 xv = *reinterpret_cast<const float4*>(xd + c4 * 4);
            float4 wv = *reinterpret_cast<const float4*>(wd + c4 * 4);
            acc = __fmaf_rn(xv.x, wv.x, acc);
            acc = __fmaf_rn(xv.y, wv.y, acc);
            acc = __fmaf_rn(xv.z, wv.z, acc);
            acc = __fmaf_rn(xv.w, wv.w, acc);
        }
    }

    // sigmoid (exp form, bit-matched) -> monotone descending key
    float em = __nv_expf(-acc);
    float s  = __fdiv_rn(1.0f, __fadd_rn(1.0f, em));
    g_keys[e * T_TOKENS + (int)rowBase + tloc] = ~__float_as_uint(s);
}

// ---------------------------------------------------------------------------
// Kernel 2: per-expert exact top-2048 (desc, ties -> lower index).
// Radix select with 8-way privatized histograms (kills hot-bin ATOMS
// serialization on the clustered sigmoid bit patterns), warp scans,
// early exit; then hybrid bitonic sort (smem j>=64, shfl j<=32).
// ---------------------------------------------------------------------------
#define K2_THREADS 1024
#define HCOPIES    8

__global__ void __launch_bounds__(K2_THREADS) k2_topk(float* __restrict__ out, int writeIdx)
{
    extern __shared__ unsigned char sm2[];
    unsigned int*        keys  = reinterpret_cast<unsigned int*>(sm2);             // 16384 u32 (64KB)
    unsigned int*        hist8 = reinterpret_cast<unsigned int*>(sm2 + 65536);     // 8 x 2048 u32 (64KB)
    unsigned int*        hscan = reinterpret_cast<unsigned int*>(sm2 + 131072);    // 2048 u32 (8KB)
    unsigned long long*  sel   = reinterpret_cast<unsigned long long*>(sm2 + 139264); // 2048 u64 (16KB)

    __shared__ unsigned int s_wsum[32];
    __shared__ unsigned long long s_pref;
    __shared__ unsigned long long s_mask;
    __shared__ int          s_want;
    __shared__ int          s_bin;
    __shared__ unsigned int s_before;
    __shared__ int          s_exact;
    __shared__ int          s_n;

    const int e    = blockIdx.x;
    const int tid  = threadIdx.x;
    const unsigned lane = tid & 31;
    const int wid  = tid >> 5;
    unsigned int* myhist = hist8 + (wid & (HCOPIES - 1)) * 2048;

    const unsigned int* gk = &g_keys[e * T_TOKENS];
    for (int i = tid; i < T_TOKENS; i += K2_THREADS)
        keys[i] = gk[i];

    if (tid == 0) { s_pref = 0ull; s_mask = 0ull; s_want = KSEL; s_exact = 0; s_n = 0; }
    __syncthreads();

    const int shifts[6] = {53, 42, 31, 20, 9, 0};
    const int nbits [6] = {11, 11, 11, 11, 11, 9};

    unsigned long long Kstar = 0ull;

    for (int lvl = 0; lvl < 6; ++lvl) {
        const int shift = shifts[lvl];
        const int nb    = 1 << nbits[lvl];
        const int wantLoc              = s_want;
        const unsigned long long mask  = s_mask;
        const unsigned long long pref  = s_pref;

        for (int i = tid; i < nb * HCOPIES; i += K2_THREADS) hist8[i] = 0u;
        __syncthreads();

        // Histogram (warp-aggregated, 8-way privatized copies).
        for (int i = tid; i < T_TOKENS; i += K2_THREADS) {
            unsigned long long K = ((unsigned long long)keys[i] << 32) | (unsigned)i;
            bool m = ((K & mask) == pref);
            unsigned active = __ballot_sync(0xffffffffu, m);
            if (m) {
                int bin = (int)((K >> shift) & (unsigned)(nb - 1));
                unsigned same = __match_any_sync(active, bin);
                if ((int)lane == (__ffs(same) - 1))
                    atomicAdd(&myhist[bin], (unsigned)__popc(same));
            }
        }
        __syncthreads();

        // Sum copies + hierarchical inclusive scan (2 bins/thread).
        {
            int b0 = 2 * tid, b1 = 2 * tid + 1;
            unsigned v0 = 0u, v1 = 0u;
            if (b0 < nb) {
#pragma unroll
                for (int c = 0; c < HCOPIES; ++c) {
                    v0 += hist8[c * 2048 + b0];
                    v1 += hist8[c * 2048 + b1];
                }
            }
            unsigned sthr = v0 + v1;
            unsigned si = sthr;
#pragma unroll
            for (int o = 1; o < 32; o <<= 1) {
                unsigned n = __shfl_up_sync(0xffffffffu, si, o);
                if (lane >= (unsigned)o) si += n;
            }
            if (lane == 31) s_wsum[wid] = si;
            __syncthreads();
            if (wid == 0) {
                unsigned w = s_wsum[lane];
                unsigned wi = w;
#pragma unroll
                for (int o = 1; o < 32; o <<= 1) {
                    unsigned n = __shfl_up_sync(0xffffffffu, wi, o);
                    if (lane >= (unsigned)o) wi += n;
                }
                s_wsum[lane] = wi - w;
            }
            __syncthreads();
            unsigned pfx = s_wsum[wid] + (si - sthr);
            if (b0 < nb) { hscan[b0] = pfx + v0; hscan[b1] = pfx + v0 + v1; }
        }
        __syncthreads();

        // Boundary bin.
        for (int i = tid; i < nb; i += K2_THREADS) {
            unsigned c = hscan[i];
            unsigned p = (i > 0) ? hscan[i - 1] : 0u;
            if ((int)c >= wantLoc && (int)p < wantLoc) {
                s_bin = i; s_before = p;
                if ((int)c == wantLoc) s_exact = 1;
            }
        }
        __syncthreads();
        if (tid == 0) {
            s_want = wantLoc - (int)s_before;
            s_pref = pref | ((unsigned long long)(unsigned)s_bin << shift);
            s_mask = mask | ((unsigned long long)(unsigned)(nb - 1) << shift);
        }
        __syncthreads();
        if (s_exact) { Kstar = s_pref | ~s_mask; break; }
    }
    if (Kstar == 0ull) Kstar = s_pref | ~s_mask;  // level-6 exit is always exact

    // Collect exactly 2048 keys <= Kstar (keys unique: index in low bits).
    for (int i = tid; i < T_TOKENS; i += K2_THREADS) {
        unsigned long long K = ((unsigned long long)keys[i] << 32) | (unsigned)i;
        bool take = (K <= Kstar);
        unsigned bal = __ballot_sync(0xffffffffu, take);
        int base = 0;
        if (lane == 0 && bal) base = atomicAdd(&s_n, __popc(bal));
        base = __shfl_sync(0xffffffffu, base, 0);
        if (take) {
            int pos = base + __popc(bal & ((1u << lane) - 1u));
            sel[pos] = K;
        }
    }
    __syncthreads();

    // ---- Hybrid bitonic sort ascending over sel[2048] ----
    const int g0 = (wid << 6) | (int)lane;
    const int g1 = g0 + 32;
    unsigned long long a = sel[g0];
    unsigned long long b = sel[g1];

    for (int k = 2; k <= KSEL; k <<= 1) {
        int j = k >> 1;
        if (j >= 64) {
            sel[g0] = a; sel[g1] = b;
            __syncthreads();
            for (; j >= 64; j >>= 1) {
                int i = ((tid & ~(j - 1)) << 1) | (tid & (j - 1));
                int l = i | j;
                unsigned long long u = sel[i];
                unsigned long long v = sel[l];
                bool asc = ((i & k) == 0);
                if ((u > v) == asc) { sel[i] = v; sel[l] = u; }
                __syncthreads();
            }
            a = sel[g0]; b = sel[g1];   // j == 32 now
        }
        for (; j >= 1; j >>= 1) {
            if (j == 32) {
                bool asc = ((g0 & k) == 0);
                if ((a > b) == asc) { unsigned long long t = a; a = b; b = t; }
            } else {
                unsigned long long pa = __shfl_xor_sync(0xffffffffu, a, j);
                unsigned long long pb = __shfl_xor_sync(0xffffffffu, b, j);
                bool lower = ((lane & (unsigned)j) == 0u);
                bool ascA  = ((g0 & k) == 0);
                bool ascB  = ((g1 & k) == 0);
                unsigned long long amin = (a < pa) ? a : pa;
                unsigned long long amax = (a < pa) ? pa : a;
                unsigned long long bmin = (b < pb) ? b : pb;
                unsigned long long bmax = (b < pb) ? pb : b;
                a = (lower == ascA) ? amin : amax;
                b = (lower == ascB) ? bmin : bmax;
            }
        }
    }

    // Emit directly from registers.
    {
        float scA = __uint_as_float(~(unsigned)(a >> 32));
        float scB = __uint_as_float(~(unsigned)(b >> 32));
        out[e * KSEL + g0] = scA;
        out[e * KSEL + g1] = scB;
        if (writeIdx) {
            out[NE * KSEL + e * KSEL + g0] = (float)(unsigned)(a & 0xffffffffu);
            out[NE * KSEL + e * KSEL + g1] = (float)(unsigned)(b & 0xffffffffu);
        }
    }
}

// ---------------------------------------------------------------------------
extern "C" void kernel_launch(void* const* d_in, const int* in_sizes, int n_in,
                              void* d_out, int out_size)
{
    const float* x = (const float*)d_in[0];   // [16384, 2048] f32
    const float* W = (const float*)d_in[1];   // [8, 2048] f32
    float* out = (float*)d_out;

    const int SMEM1 = (NE * WP + TILE_T * XPITCH) * (int)sizeof(float); // 99456
    const int SMEM2 = 65536 + 65536 + 8192 + 16384;                     // 155648

    cudaFuncSetAttribute(k1_gemv, cudaFuncAttributeMaxDynamicSharedMemorySize, SMEM1);
    cudaFuncSetAttribute(k2_topk, cudaFuncAttributeMaxDynamicSharedMemorySize, SMEM2);

    const int writeIdx = (out_size >= 2 * NE * KSEL) ? 1 : 0;

    k1_gemv<<<T_TOKENS / TILE_T, K1_THREADS, SMEM1>>>(x, W);
    k2_topk<<<NE, K2_THREADS, SMEM2>>>(out, writeIdx);
}